// round 7
// baseline (speedup 1.0000x reference)
#include <cuda_runtime.h>
#include <cstdint>

// QuantumDotProductCircuit — single fused kernel.
//   ov(b) = a(b)^T M b(b),  score = |ov|^2, out = (1+score)/2
// a,b are real Kronecker product states from RY(tanh(x)*pi) on |0>,
// M = U_q^dagger U_k (16x16 complex) from W_q,W_k — recomputed per block
// (cheap, overlaps the input-load DRAM latency; removes the prep kernel
// launch + graph gap entirely).

__device__ __forceinline__ unsigned long long pk2(float lo, float hi) {
    unsigned long long r;
    asm("mov.b64 %0, {%1, %2};" : "=l"(r) : "f"(lo), "f"(hi));
    return r;
}
__device__ __forceinline__ float2 upk2(unsigned long long v) {
    float2 r;
    asm("mov.b64 {%0, %1}, %2;" : "=f"(r.x), "=f"(r.y) : "l"(v));
    return r;
}
__device__ __forceinline__ unsigned long long fma2(unsigned long long a,
                                                   unsigned long long b,
                                                   unsigned long long c) {
    unsigned long long d;
    asm("fma.rn.f32x2 %0, %1, %2, %3;" : "=l"(d) : "l"(a), "l"(b), "l"(c));
    return d;
}

// fast tanh: (e^{2x}-1)/(e^{2x}+1), EX2 + RCP.approx. rel err ~1e-6.
__device__ __forceinline__ float fast_tanh(float x) {
    x = fminf(fmaxf(x, -9.0f), 9.0f);
    float e = __expf(2.0f * x);
    return __fdividef(e - 1.0f, e + 1.0f);
}

// Build a-side factors and b-side packed pairs for one element.
__device__ __forceinline__ void build_ab(float4 qv, float4 kv,
                                         float* a01, float* a23,
                                         unsigned long long* bp) {
    const float HP = 1.5707963267948966f;  // pi/2
    float cs[4], sn[4];
    __sincosf(fast_tanh(qv.x) * HP, &sn[0], &cs[0]);
    __sincosf(fast_tanh(qv.y) * HP, &sn[1], &cs[1]);
    __sincosf(fast_tanh(qv.z) * HP, &sn[2], &cs[2]);
    __sincosf(fast_tanh(qv.w) * HP, &sn[3], &cs[3]);
    a01[0] = cs[0]*cs[1]; a01[1] = cs[0]*sn[1]; a01[2] = sn[0]*cs[1]; a01[3] = sn[0]*sn[1];
    a23[0] = cs[2]*cs[3]; a23[1] = cs[2]*sn[3]; a23[2] = sn[2]*cs[3]; a23[3] = sn[2]*sn[3];

    __sincosf(fast_tanh(kv.x) * HP, &sn[0], &cs[0]);
    __sincosf(fast_tanh(kv.y) * HP, &sn[1], &cs[1]);
    __sincosf(fast_tanh(kv.z) * HP, &sn[2], &cs[2]);
    __sincosf(fast_tanh(kv.w) * HP, &sn[3], &cs[3]);
    float b01[4] = {cs[0]*cs[1], cs[0]*sn[1], sn[0]*cs[1], sn[0]*sn[1]};
    float b23[4] = {cs[2]*cs[3], cs[2]*sn[3], sn[2]*cs[3], sn[2]*sn[3]};
#pragma unroll
    for (int p = 0; p < 8; p++) {
        int j0 = 2 * p, j1 = 2 * p + 1;
        bp[p] = pk2(b01[j0 >> 2] * b23[j0 & 3], b01[j1 >> 2] * b23[j1 & 3]);
    }
}

// Fused contraction for two elements sharing each M load.
// MshR/MshI: split re/im planes, row-major float[256] viewed as ulonglong2[64].
__device__ __forceinline__ void contract2(
        const ulonglong2* __restrict__ MshR, const ulonglong2* __restrict__ MshI,
        const float* a01_0, const float* a23_0, const unsigned long long* bp0,
        const float* a01_1, const float* a23_1, const unsigned long long* bp1,
        float* out0, float* out1) {
    unsigned long long ovr0 = 0ULL, ovi0 = 0ULL, ovr1 = 0ULL, ovi1 = 0ULL;
#pragma unroll
    for (int i = 0; i < 16; i++) {
        unsigned long long tr0 = 0ULL, ti0 = 0ULL, tr1 = 0ULL, ti1 = 0ULL;
#pragma unroll
        for (int c = 0; c < 4; c++) {
            ulonglong2 mr = MshR[i * 4 + c];
            ulonglong2 mi = MshI[i * 4 + c];
            tr0 = fma2(mr.x, bp0[2 * c + 0], tr0);
            tr1 = fma2(mr.x, bp1[2 * c + 0], tr1);
            ti0 = fma2(mi.x, bp0[2 * c + 0], ti0);
            ti1 = fma2(mi.x, bp1[2 * c + 0], ti1);
            tr0 = fma2(mr.y, bp0[2 * c + 1], tr0);
            tr1 = fma2(mr.y, bp1[2 * c + 1], tr1);
            ti0 = fma2(mi.y, bp0[2 * c + 1], ti0);
            ti1 = fma2(mi.y, bp1[2 * c + 1], ti1);
        }
        float av0 = a01_0[i >> 2] * a23_0[i & 3];
        float av1 = a01_1[i >> 2] * a23_1[i & 3];
        unsigned long long av0p = pk2(av0, av0);
        unsigned long long av1p = pk2(av1, av1);
        ovr0 = fma2(av0p, tr0, ovr0);
        ovi0 = fma2(av0p, ti0, ovi0);
        ovr1 = fma2(av1p, tr1, ovr1);
        ovi1 = fma2(av1p, ti1, ovi1);
    }
    {
        float2 r2 = upk2(ovr0), i2 = upk2(ovi0);
        float re = r2.x + r2.y, im = i2.x + i2.y;
        *out0 = fmaf(0.5f, fmaf(re, re, im * im), 0.5f);
    }
    {
        float2 r2 = upk2(ovr1), i2 = upk2(ovi1);
        float re = r2.x + r2.y, im = i2.x + i2.y;
        *out1 = fmaf(0.5f, fmaf(re, re, im * im), 0.5f);
    }
}

// ---------------------------------------------------------------------------
// Fused kernel: 512 elements per 128-thread block (4/thread, 2 fused pairs).
// All 8 input LDGs issued first; while they drain, lanes <32 simulate the
// Rot+CNOT layers to build U_q/U_k (wire w -> index bit 3-w), then all 128
// threads form M = U_q^dagger U_k (2 entries each) in SMEM.
// ---------------------------------------------------------------------------
__global__ void __launch_bounds__(128) qdp_fused(
        const float4* __restrict__ q4, const float4* __restrict__ k4,
        const float* __restrict__ Wq, const float* __restrict__ Wk,
        float* __restrict__ out, int B) {
    __shared__ float2 Ush[2][16][16];     // [matrix][row t][column c]
    __shared__ ulonglong2 MshR[64];       // M real plane, row-major
    __shared__ ulonglong2 MshI[64];       // M imag plane

    const int tid = threadIdx.x;
    const int base = blockIdx.x * 512;
    const int e0r = base + tid;
    const int e1r = base + 128 + tid;
    const int e2r = base + 256 + tid;
    const int e3r = base + 384 + tid;
    const int e0 = (e0r < B) ? e0r : (B - 1);
    const int e1 = (e1r < B) ? e1r : (B - 1);
    const int e2 = (e2r < B) ? e2r : (B - 1);
    const int e3 = (e3r < B) ? e3r : (B - 1);

    // ---- 1) Front-batch all input loads (rows are 16 float4, take #0) ----
    float4 q0 = __ldcs(&q4[(size_t)e0 * 16]);
    float4 k0 = __ldcs(&k4[(size_t)e0 * 16]);
    float4 q1 = __ldcs(&q4[(size_t)e1 * 16]);
    float4 k1 = __ldcs(&k4[(size_t)e1 * 16]);
    float4 q2 = __ldcs(&q4[(size_t)e2 * 16]);
    float4 k2 = __ldcs(&k4[(size_t)e2 * 16]);
    float4 q3 = __ldcs(&q4[(size_t)e3 * 16]);
    float4 k3 = __ldcs(&k4[(size_t)e3 * 16]);

    // ---- 2) Warp 0: simulate circuit on each basis state -> U ----
    if (tid < 32) {
        int m = tid >> 4;       // 0 = q, 1 = k
        int c = tid & 15;       // column = input basis state
        const float* W = m ? Wk : Wq;

        float vr[16], vi[16];
#pragma unroll
        for (int s = 0; s < 16; s++) { vr[s] = (s == c) ? 1.0f : 0.0f; vi[s] = 0.0f; }

#pragma unroll
        for (int layer = 0; layer < 2; layer++) {
#pragma unroll
            for (int w = 0; w < 4; w++) {
                float phi = W[layer * 12 + w * 3 + 0];
                float th  = W[layer * 12 + w * 3 + 1];
                float om  = W[layer * 12 + w * 3 + 2];
                float cth, sth; __sincosf(0.5f * th, &sth, &cth);
                float sA, cA, sB, cB;
                __sincosf(0.5f * (phi + om), &sA, &cA);
                __sincosf(0.5f * (phi - om), &sB, &cB);
                float u00r =  cA * cth, u00i = -sA * cth;
                float u01r = -cB * sth, u01i = -sB * sth;
                float u10r =  cB * sth, u10i = -sB * sth;
                float u11r =  cA * cth, u11i =  sA * cth;
                const int st = 8 >> w;
#pragma unroll
                for (int s = 0; s < 16; s++) {
                    if (!(s & st)) {
                        const int s1 = s | st;
                        float xr = vr[s], xi = vi[s], yr = vr[s1], yi = vi[s1];
                        vr[s]  = u00r * xr - u00i * xi + u01r * yr - u01i * yi;
                        vi[s]  = u00r * xi + u00i * xr + u01r * yi + u01i * yr;
                        vr[s1] = u10r * xr - u10i * xi + u11r * yr - u11i * yi;
                        vi[s1] = u10r * xi + u10i * xr + u11r * yi + u11i * yr;
                    }
                }
            }
#pragma unroll
            for (int w = 0; w < 3; w++) {
                const int cm = 8 >> w, tm = 4 >> w;
#pragma unroll
                for (int s = 0; s < 16; s++) {
                    if ((s & cm) && !(s & tm)) {
                        const int s1 = s | tm;
                        float tr = vr[s], ti = vi[s];
                        vr[s] = vr[s1]; vi[s] = vi[s1];
                        vr[s1] = tr;    vi[s1] = ti;
                    }
                }
            }
        }
#pragma unroll
        for (int t = 0; t < 16; t++) Ush[m][t][c] = make_float2(vr[t], vi[t]);
    }
    __syncthreads();

    // ---- 3) All 128 threads: 2 M entries each. M[i][j] = sum_t conj(Uq[t][i]) Uk[t][j]
    {
        float* gmr = (float*)MshR;
        float* gmi = (float*)MshI;
#pragma unroll
        for (int e = 2 * tid; e < 2 * tid + 2; e++) {
            int i = e >> 4, j = e & 15;
            float mr = 0.0f, mi = 0.0f;
#pragma unroll
            for (int t = 0; t < 16; t++) {
                float2 uq = Ush[0][t][i];
                float2 uk = Ush[1][t][j];
                mr += uq.x * uk.x + uq.y * uk.y;
                mi += uq.x * uk.y - uq.y * uk.x;
            }
            gmr[e] = mr;
            gmi[e] = mi;
        }
    }
    __syncthreads();

    // ---- 4) Group 0 (e0, e1): transcendentals + fused contraction ----
    {
        float a01_0[4], a23_0[4], a01_1[4], a23_1[4];
        unsigned long long bp0[8], bp1[8];
        build_ab(q0, k0, a01_0, a23_0, bp0);
        build_ab(q1, k1, a01_1, a23_1, bp1);
        float o0, o1;
        contract2(MshR, MshI, a01_0, a23_0, bp0, a01_1, a23_1, bp1, &o0, &o1);
        if (e0r < B) out[e0r] = o0;
        if (e1r < B) out[e1r] = o1;
    }

    // ---- 5) Group 1 (e2, e3) ----
    {
        float a01_0[4], a23_0[4], a01_1[4], a23_1[4];
        unsigned long long bp0[8], bp1[8];
        build_ab(q2, k2, a01_0, a23_0, bp0);
        build_ab(q3, k3, a01_1, a23_1, bp1);
        float o0, o1;
        contract2(MshR, MshI, a01_0, a23_0, bp0, a01_1, a23_1, bp1, &o0, &o1);
        if (e2r < B) out[e2r] = o0;
        if (e3r < B) out[e3r] = o1;
    }
}

extern "C" void kernel_launch(void* const* d_in, const int* in_sizes, int n_in,
                              void* d_out, int out_size) {
    const float* q  = (const float*)d_in[0];
    const float* k  = (const float*)d_in[1];
    const float* Wq = (const float*)d_in[2];
    const float* Wk = (const float*)d_in[3];
    int B = in_sizes[0] / 64;

    int nblk = (B + 511) / 512;
    qdp_fused<<<nblk, 128>>>((const float4*)q, (const float4*)k,
                             Wq, Wk, (float*)d_out, B);
}

// round 8
// speedup vs baseline: 2.2317x; 2.2317x over previous
#include <cuda_runtime.h>
#include <cstdint>

// QuantumDotProductCircuit:
//   ov(b) = a(b)^T M b(b),  score = |ov|^2, out = (1+score)/2
// a,b are real Kronecker product states from RY(tanh(x)*pi) on |0>,
// M = U_q^dagger U_k is a fixed 16x16 complex matrix built from W_q,W_k.
// Two kernels; PDL overlaps main's input loads with prep + launch gap.

__device__ ulonglong2 g_M[128];  // 16x16 complex, interleaved (re,im), row-major

__device__ __forceinline__ unsigned long long pk2(float lo, float hi) {
    unsigned long long r;
    asm("mov.b64 %0, {%1, %2};" : "=l"(r) : "f"(lo), "f"(hi));
    return r;
}
__device__ __forceinline__ float2 upk2(unsigned long long v) {
    float2 r;
    asm("mov.b64 {%0, %1}, %2;" : "=f"(r.x), "=f"(r.y) : "l"(v));
    return r;
}
__device__ __forceinline__ unsigned long long fma2(unsigned long long a,
                                                   unsigned long long b,
                                                   unsigned long long c) {
    unsigned long long d;
    asm("fma.rn.f32x2 %0, %1, %2, %3;" : "=l"(d) : "l"(a), "l"(b), "l"(c));
    return d;
}
__device__ __forceinline__ unsigned long long add2(unsigned long long a,
                                                   unsigned long long b) {
    unsigned long long d;
    asm("add.rn.f32x2 %0, %1, %2;" : "=l"(d) : "l"(a), "l"(b));
    return d;
}

// fast tanh: (e^{2x}-1)/(e^{2x}+1), EX2 + RCP.approx. rel err ~1e-6.
__device__ __forceinline__ float fast_tanh(float x) {
    x = fminf(fmaxf(x, -9.0f), 9.0f);
    float e = __expf(2.0f * x);
    return __fdividef(e - 1.0f, e + 1.0f);
}

// ---------------------------------------------------------------------------
// Prep kernel: build U_q, U_k (16x16) by simulating the Rot+CNOT layers on
// each basis state, then M = U_q^dagger U_k. One block, 256 threads.
// Wire w maps to index bit (3-w) (reference reshape puts wire 0 as MSB).
// Triggers programmatic launch completion after M is globally visible.
// ---------------------------------------------------------------------------
__global__ void qdp_prep(const float* __restrict__ Wq, const float* __restrict__ Wk) {
    __shared__ float2 U[2][16][16];  // [matrix][row t][column c]
    int tid = threadIdx.x;

    if (tid < 32) {
        int m = tid >> 4;       // 0 = q, 1 = k
        int c = tid & 15;       // column = input basis state
        const float* W = m ? Wk : Wq;

        float vr[16], vi[16];
#pragma unroll
        for (int s = 0; s < 16; s++) { vr[s] = (s == c) ? 1.0f : 0.0f; vi[s] = 0.0f; }

#pragma unroll
        for (int layer = 0; layer < 2; layer++) {
#pragma unroll
            for (int w = 0; w < 4; w++) {
                float phi = W[layer * 12 + w * 3 + 0];
                float th  = W[layer * 12 + w * 3 + 1];
                float om  = W[layer * 12 + w * 3 + 2];
                float cth, sth; __sincosf(0.5f * th, &sth, &cth);
                float sA, cA, sB, cB;
                __sincosf(0.5f * (phi + om), &sA, &cA);
                __sincosf(0.5f * (phi - om), &sB, &cB);
                float u00r =  cA * cth, u00i = -sA * cth;
                float u01r = -cB * sth, u01i = -sB * sth;
                float u10r =  cB * sth, u10i = -sB * sth;
                float u11r =  cA * cth, u11i =  sA * cth;
                const int st = 8 >> w;
#pragma unroll
                for (int s = 0; s < 16; s++) {
                    if (!(s & st)) {
                        const int s1 = s | st;
                        float xr = vr[s], xi = vi[s], yr = vr[s1], yi = vi[s1];
                        vr[s]  = u00r * xr - u00i * xi + u01r * yr - u01i * yi;
                        vi[s]  = u00r * xi + u00i * xr + u01r * yi + u01i * yr;
                        vr[s1] = u10r * xr - u10i * xi + u11r * yr - u11i * yi;
                        vi[s1] = u10r * xi + u10i * xr + u11r * yi + u11i * yr;
                    }
                }
            }
#pragma unroll
            for (int w = 0; w < 3; w++) {
                const int cm = 8 >> w, tm = 4 >> w;
#pragma unroll
                for (int s = 0; s < 16; s++) {
                    if ((s & cm) && !(s & tm)) {
                        const int s1 = s | tm;
                        float tr = vr[s], ti = vi[s];
                        vr[s] = vr[s1]; vi[s] = vi[s1];
                        vr[s1] = tr;    vi[s1] = ti;
                    }
                }
            }
        }
#pragma unroll
        for (int t = 0; t < 16; t++) U[m][t][c] = make_float2(vr[t], vi[t]);
    }
    __syncthreads();

    // M[i][j] = sum_t conj(Uq[t][i]) * Uk[t][j]
    int i = tid >> 4, j = tid & 15;
    float mr = 0.0f, mi = 0.0f;
#pragma unroll
    for (int t = 0; t < 16; t++) {
        float2 q = U[0][t][i];
        float2 k = U[1][t][j];
        mr += q.x * k.x + q.y * k.y;
        mi += q.x * k.y - q.y * k.x;
    }
    float* gm = (float*)g_M;
    gm[2 * (i * 16 + j) + 0] = mr;
    gm[2 * (i * 16 + j) + 1] = mi;

    // Make M visible, then allow the dependent main kernel to launch.
    __threadfence();
    __syncthreads();
    cudaTriggerProgrammaticLaunchCompletion();
}

// ---------------------------------------------------------------------------
// Main kernel (R1 structure — measured best): one thread per element,
// 256-thread blocks. Input LDGs issued BEFORE the grid-dependency sync so
// they overlap prep's tail; M -> SMEM after the sync.
// ---------------------------------------------------------------------------
__global__ void qdp_main(const float4* __restrict__ q4, const float4* __restrict__ k4,
                         float* __restrict__ out, int B) {
    __shared__ ulonglong2 Msh[128];
    int tid = threadIdx.x;
    int idx = blockIdx.x * 256 + tid;
    if (idx >= B) idx = B - 1;

    // rows are 64 floats = 16 float4; we need float4 #0 (overlaps prep via PDL)
    float4 qv = q4[(size_t)idx * 16];
    float4 kv = k4[(size_t)idx * 16];

    // Wait for prep's g_M to be complete/visible.
    cudaGridDependencySynchronize();

    if (tid < 128) Msh[tid] = g_M[tid];
    __syncthreads();

    const float HP = 1.5707963267948966f;  // pi/2 (half-angle scale)
    float cs[4], sn[4];
    __sincosf(fast_tanh(qv.x) * HP, &sn[0], &cs[0]);
    __sincosf(fast_tanh(qv.y) * HP, &sn[1], &cs[1]);
    __sincosf(fast_tanh(qv.z) * HP, &sn[2], &cs[2]);
    __sincosf(fast_tanh(qv.w) * HP, &sn[3], &cs[3]);
    float a01[4] = {cs[0]*cs[1], cs[0]*sn[1], sn[0]*cs[1], sn[0]*sn[1]};
    float a23[4] = {cs[2]*cs[3], cs[2]*sn[3], sn[2]*cs[3], sn[2]*sn[3]};

    __sincosf(fast_tanh(kv.x) * HP, &sn[0], &cs[0]);
    __sincosf(fast_tanh(kv.y) * HP, &sn[1], &cs[1]);
    __sincosf(fast_tanh(kv.z) * HP, &sn[2], &cs[2]);
    __sincosf(fast_tanh(kv.w) * HP, &sn[3], &cs[3]);
    float b01[4] = {cs[0]*cs[1], cs[0]*sn[1], sn[0]*cs[1], sn[0]*sn[1]};
    float b23[4] = {cs[2]*cs[3], cs[2]*sn[3], sn[2]*cs[3], sn[2]*sn[3]};

    unsigned long long bp[16];
#pragma unroll
    for (int j = 0; j < 16; j++) {
        float v = b01[j >> 2] * b23[j & 3];
        bp[j] = pk2(v, v);
    }

    // ov = sum_i av[i] * (sum_j M[i][j] * b[j]), packed (re,im) lanes
    unsigned long long ov0 = 0ULL, ov1 = 0ULL;
#pragma unroll
    for (int i = 0; i < 16; i++) {
        unsigned long long t0 = 0ULL, t1 = 0ULL;
#pragma unroll
        for (int jj = 0; jj < 8; jj++) {
            ulonglong2 m = Msh[i * 8 + jj];     // two complex entries
            t0 = fma2(m.x, bp[2 * jj + 0], t0);
            t1 = fma2(m.y, bp[2 * jj + 1], t1);
        }
        float avi = a01[i >> 2] * a23[i & 3];
        unsigned long long avp = pk2(avi, avi);
        unsigned long long s = add2(t0, t1);
        if (i & 1) ov1 = fma2(avp, s, ov1);
        else       ov0 = fma2(avp, s, ov0);
    }
    float2 o = upk2(add2(ov0, ov1));
    float score = o.x * o.x + o.y * o.y;
    out[idx] = fmaf(0.5f, score, 0.5f);
}

extern "C" void kernel_launch(void* const* d_in, const int* in_sizes, int n_in,
                              void* d_out, int out_size) {
    const float* q  = (const float*)d_in[0];
    const float* k  = (const float*)d_in[1];
    const float* Wq = (const float*)d_in[2];
    const float* Wk = (const float*)d_in[3];
    int B = in_sizes[0] / 64;
    int nblk = (B + 255) / 256;

    qdp_prep<<<1, 256>>>(Wq, Wk);

    // Launch main with programmatic stream serialization (PDL) so its input
    // loads overlap prep's tail + launch latency. Fall back to a plain
    // launch if the attribute launch fails.
    cudaLaunchConfig_t cfg = {};
    cfg.gridDim  = dim3((unsigned)nblk, 1, 1);
    cfg.blockDim = dim3(256, 1, 1);
    cudaLaunchAttribute attrs[1];
    attrs[0].id = cudaLaunchAttributeProgrammaticStreamSerialization;
    attrs[0].val.programmaticStreamSerializationAllowed = 1;
    cfg.attrs = attrs;
    cfg.numAttrs = 1;

    cudaError_t err = cudaLaunchKernelEx(&cfg, qdp_main,
                                         (const float4*)q, (const float4*)k,
                                         (float*)d_out, B);
    if (err != cudaSuccess) {
        qdp_main<<<nblk, 256>>>((const float4*)q, (const float4*)k,
                                (float*)d_out, B);
    }
}

// round 13
// speedup vs baseline: 2.2354x; 1.0017x over previous
#include <cuda_runtime.h>
#include <cstdint>

// QuantumDotProductCircuit:
//   ov(b) = a(b)^T M b(b),  score = |ov|^2, out = (1+score)/2
// a,b are real Kronecker product states from RY(tanh(x)*pi) on |0>,
// M = U_q^dagger U_k is a fixed 16x16 complex matrix built from W_q,W_k.
// Two kernels; PDL collapses the inter-kernel gap. Main kernel = R1
// structure (measured at the strided-DRAM pattern floor ~17.3us).

__device__ ulonglong2 g_M[128];  // 16x16 complex, interleaved (re,im), row-major

__device__ __forceinline__ unsigned long long pk2(float lo, float hi) {
    unsigned long long r;
    asm("mov.b64 %0, {%1, %2};" : "=l"(r) : "f"(lo), "f"(hi));
    return r;
}
__device__ __forceinline__ float2 upk2(unsigned long long v) {
    float2 r;
    asm("mov.b64 {%0, %1}, %2;" : "=f"(r.x), "=f"(r.y) : "l"(v));
    return r;
}
__device__ __forceinline__ unsigned long long fma2(unsigned long long a,
                                                   unsigned long long b,
                                                   unsigned long long c) {
    unsigned long long d;
    asm("fma.rn.f32x2 %0, %1, %2, %3;" : "=l"(d) : "l"(a), "l"(b), "l"(c));
    return d;
}
__device__ __forceinline__ unsigned long long add2(unsigned long long a,
                                                   unsigned long long b) {
    unsigned long long d;
    asm("add.rn.f32x2 %0, %1, %2;" : "=l"(d) : "l"(a), "l"(b));
    return d;
}

// fast tanh: (e^{2x}-1)/(e^{2x}+1), EX2 + RCP.approx. rel err ~1e-6.
__device__ __forceinline__ float fast_tanh(float x) {
    x = fminf(fmaxf(x, -9.0f), 9.0f);
    float e = __expf(2.0f * x);
    return __fdividef(e - 1.0f, e + 1.0f);
}

// ---------------------------------------------------------------------------
// Prep kernel: build U_q, U_k (16x16) by simulating the Rot+CNOT layers on
// each basis state, then M = U_q^dagger U_k. One block, 256 threads.
// Wire w maps to index bit (3-w) (reference reshape puts wire 0 as MSB).
// Triggers programmatic launch completion after M is globally visible.
// ---------------------------------------------------------------------------
__global__ void qdp_prep(const float* __restrict__ Wq, const float* __restrict__ Wk) {
    __shared__ float2 U[2][16][16];  // [matrix][row t][column c]
    int tid = threadIdx.x;

    if (tid < 32) {
        int m = tid >> 4;       // 0 = q, 1 = k
        int c = tid & 15;       // column = input basis state
        const float* W = m ? Wk : Wq;

        float vr[16], vi[16];
#pragma unroll
        for (int s = 0; s < 16; s++) { vr[s] = (s == c) ? 1.0f : 0.0f; vi[s] = 0.0f; }

#pragma unroll
        for (int layer = 0; layer < 2; layer++) {
#pragma unroll
            for (int w = 0; w < 4; w++) {
                float phi = W[layer * 12 + w * 3 + 0];
                float th  = W[layer * 12 + w * 3 + 1];
                float om  = W[layer * 12 + w * 3 + 2];
                float cth, sth; __sincosf(0.5f * th, &sth, &cth);
                float sA, cA, sB, cB;
                __sincosf(0.5f * (phi + om), &sA, &cA);
                __sincosf(0.5f * (phi - om), &sB, &cB);
                float u00r =  cA * cth, u00i = -sA * cth;
                float u01r = -cB * sth, u01i = -sB * sth;
                float u10r =  cB * sth, u10i = -sB * sth;
                float u11r =  cA * cth, u11i =  sA * cth;
                const int st = 8 >> w;
#pragma unroll
                for (int s = 0; s < 16; s++) {
                    if (!(s & st)) {
                        const int s1 = s | st;
                        float xr = vr[s], xi = vi[s], yr = vr[s1], yi = vi[s1];
                        vr[s]  = u00r * xr - u00i * xi + u01r * yr - u01i * yi;
                        vi[s]  = u00r * xi + u00i * xr + u01r * yi + u01i * yr;
                        vr[s1] = u10r * xr - u10i * xi + u11r * yr - u11i * yi;
                        vi[s1] = u10r * xi + u10i * xr + u11r * yi + u11i * yr;
                    }
                }
            }
#pragma unroll
            for (int w = 0; w < 3; w++) {
                const int cm = 8 >> w, tm = 4 >> w;
#pragma unroll
                for (int s = 0; s < 16; s++) {
                    if ((s & cm) && !(s & tm)) {
                        const int s1 = s | tm;
                        float tr = vr[s], ti = vi[s];
                        vr[s] = vr[s1]; vi[s] = vi[s1];
                        vr[s1] = tr;    vi[s1] = ti;
                    }
                }
            }
        }
#pragma unroll
        for (int t = 0; t < 16; t++) U[m][t][c] = make_float2(vr[t], vi[t]);
    }
    __syncthreads();

    // M[i][j] = sum_t conj(Uq[t][i]) * Uk[t][j]
    int i = tid >> 4, j = tid & 15;
    float mr = 0.0f, mi = 0.0f;
#pragma unroll
    for (int t = 0; t < 16; t++) {
        float2 q = U[0][t][i];
        float2 k = U[1][t][j];
        mr += q.x * k.x + q.y * k.y;
        mi += q.x * k.y - q.y * k.x;
    }
    float* gm = (float*)g_M;
    gm[2 * (i * 16 + j) + 0] = mr;
    gm[2 * (i * 16 + j) + 1] = mi;

    // Make M visible, then allow the dependent main kernel to launch.
    __threadfence();
    __syncthreads();
    cudaTriggerProgrammaticLaunchCompletion();
}

// ---------------------------------------------------------------------------
// Main kernel: R1 structure (one thread/element, 256-thr blocks).
// Grid-dependency sync happens FIRST so no values are live across it
// (keeps regs ~48 / occ ~50% — the measured-best configuration).
// ---------------------------------------------------------------------------
__global__ void __launch_bounds__(256) qdp_main(
        const float4* __restrict__ q4, const float4* __restrict__ k4,
        float* __restrict__ out, int B) {
    // Wait for prep's g_M before anything else (PDL dependency).
    cudaGridDependencySynchronize();

    __shared__ ulonglong2 Msh[128];
    int tid = threadIdx.x;
    if (tid < 128) Msh[tid] = g_M[tid];
    __syncthreads();

    int idx = blockIdx.x * 256 + tid;
    if (idx >= B) idx = B - 1;

    // rows are 64 floats = 16 float4; we need float4 #0 of each row
    float4 qv = q4[(size_t)idx * 16];
    float4 kv = k4[(size_t)idx * 16];

    const float HP = 1.5707963267948966f;  // pi/2 (half-angle scale)
    float cs[4], sn[4];
    __sincosf(fast_tanh(qv.x) * HP, &sn[0], &cs[0]);
    __sincosf(fast_tanh(qv.y) * HP, &sn[1], &cs[1]);
    __sincosf(fast_tanh(qv.z) * HP, &sn[2], &cs[2]);
    __sincosf(fast_tanh(qv.w) * HP, &sn[3], &cs[3]);
    float a01[4] = {cs[0]*cs[1], cs[0]*sn[1], sn[0]*cs[1], sn[0]*sn[1]};
    float a23[4] = {cs[2]*cs[3], cs[2]*sn[3], sn[2]*cs[3], sn[2]*sn[3]};

    __sincosf(fast_tanh(kv.x) * HP, &sn[0], &cs[0]);
    __sincosf(fast_tanh(kv.y) * HP, &sn[1], &cs[1]);
    __sincosf(fast_tanh(kv.z) * HP, &sn[2], &cs[2]);
    __sincosf(fast_tanh(kv.w) * HP, &sn[3], &cs[3]);
    float b01[4] = {cs[0]*cs[1], cs[0]*sn[1], sn[0]*cs[1], sn[0]*sn[1]};
    float b23[4] = {cs[2]*cs[3], cs[2]*sn[3], sn[2]*cs[3], sn[2]*sn[3]};

    unsigned long long bp[16];
#pragma unroll
    for (int j = 0; j < 16; j++) {
        float v = b01[j >> 2] * b23[j & 3];
        bp[j] = pk2(v, v);
    }

    // ov = sum_i av[i] * (sum_j M[i][j] * b[j]), packed (re,im) lanes
    unsigned long long ov0 = 0ULL, ov1 = 0ULL;
#pragma unroll
    for (int i = 0; i < 16; i++) {
        unsigned long long t0 = 0ULL, t1 = 0ULL;
#pragma unroll
        for (int jj = 0; jj < 8; jj++) {
            ulonglong2 m = Msh[i * 8 + jj];     // two complex entries
            t0 = fma2(m.x, bp[2 * jj + 0], t0);
            t1 = fma2(m.y, bp[2 * jj + 1], t1);
        }
        float avi = a01[i >> 2] * a23[i & 3];
        unsigned long long avp = pk2(avi, avi);
        unsigned long long s = add2(t0, t1);
        if (i & 1) ov1 = fma2(avp, s, ov1);
        else       ov0 = fma2(avp, s, ov0);
    }
    float2 o = upk2(add2(ov0, ov1));
    float score = o.x * o.x + o.y * o.y;
    out[idx] = fmaf(0.5f, score, 0.5f);
}

extern "C" void kernel_launch(void* const* d_in, const int* in_sizes, int n_in,
                              void* d_out, int out_size) {
    const float* q  = (const float*)d_in[0];
    const float* k  = (const float*)d_in[1];
    const float* Wq = (const float*)d_in[2];
    const float* Wk = (const float*)d_in[3];
    int B = in_sizes[0] / 64;
    int nblk = (B + 255) / 256;

    qdp_prep<<<1, 256>>>(Wq, Wk);

    // PDL launch: main's blocks spin up while prep finishes; dependency is
    // released by prep's cudaTriggerProgrammaticLaunchCompletion().
    cudaLaunchConfig_t cfg = {};
    cfg.gridDim  = dim3((unsigned)nblk, 1, 1);
    cfg.blockDim = dim3(256, 1, 1);
    cudaLaunchAttribute attrs[1];
    attrs[0].id = cudaLaunchAttributeProgrammaticStreamSerialization;
    attrs[0].val.programmaticStreamSerializationAllowed = 1;
    cfg.attrs = attrs;
    cfg.numAttrs = 1;

    cudaError_t err = cudaLaunchKernelEx(&cfg, qdp_main,
                                         (const float4*)q, (const float4*)k,
                                         (float*)d_out, B);
    if (err != cudaSuccess) {
        qdp_main<<<nblk, 256>>>((const float4*)q, (const float4*)k,
                                (float*)d_out, B);
    }
}